// round 11
// baseline (speedup 1.0000x reference)
#include <cuda_runtime.h>
#include <math.h>

#define N_PTS 2048
#define DIMS 64
#define EPSV 0.1f
#define INV_EPS 10.0f
#define LOG2E 1.4426950408889634f
#define LN2 0.6931471805599453f
#define SCALE2 (INV_EPS * LOG2E)        /* nat -> exp2 domain incl. 1/eps */
#define ITERS 100
#define THRESH 0.1f

#define SOLVE_BLOCKS 128          // 128 blocks x 16 warps = 2048 warps = one per row
#define SOLVE_THREADS 512

// ---------------- device scratch (static, allocation-free) ----------------
__device__ __align__(16) float g_Ce[N_PTS * N_PTS];   // -C/eps*log2e, row-major [i][j]
__device__ __align__(16) float g_Ct[N_PTS * N_PTS];   // transpose [j][i]
__device__ __align__(16) float g_usc[N_PTS];          // u/eps*log2e
__device__ __align__(16) float g_vsc[N_PTS];          // v/eps*log2e
__device__ float g_cost_part[N_PTS];
__device__ unsigned long long g_flag[SOLVE_BLOCKS];   // packed (float partial << 32 | epoch)

// ---------------- fast exp2/log2 ----------------
__device__ __forceinline__ float ex2(float x) {
    float r; asm("ex2.approx.ftz.f32 %0, %1;" : "=f"(r) : "f"(x)); return r;
}
__device__ __forceinline__ float lg2(float x) {
    float r; asm("lg2.approx.f32 %0, %1;" : "=f"(r) : "f"(x)); return r;
}

// ---------------- flag-array grid barrier, optional fused sum-reduce ----------------
// Every block stores its epoch(+payload) to its own slot; every block's first
// 128 threads each poll one slot. No atomic serialization, no release hop.
template <bool PAYLOAD>
__device__ __forceinline__ float bar_sync(unsigned epoch, float payload) {
    __shared__ float red[4];
    __syncthreads();
    __threadfence();
    if (threadIdx.x == 0) {
        unsigned long long v =
            ((unsigned long long)__float_as_uint(payload) << 32) | (unsigned long long)epoch;
        asm volatile("st.release.gpu.global.u64 [%0], %1;"
                     :: "l"(g_flag + blockIdx.x), "l"(v) : "memory");
    }
    if (threadIdx.x < SOLVE_BLOCKS) {
        unsigned long long v;
        do {
            asm volatile("ld.acquire.gpu.global.u64 %0, [%1];"
                         : "=l"(v) : "l"(g_flag + threadIdx.x) : "memory");
        } while ((unsigned)v != epoch);
        if (PAYLOAD) {
            float ps = __uint_as_float((unsigned)(v >> 32));
#pragma unroll
            for (int o = 16; o; o >>= 1) ps += __shfl_xor_sync(0xffffffffu, ps, o);
            if ((threadIdx.x & 31) == 0) red[threadIdx.x >> 5] = ps;
        }
    }
    __syncthreads();
    if (PAYLOAD) return red[0] + red[1] + red[2] + red[3];
    return 0.f;
}

// ---------------- cost matrix: Ce2[i][j] = -||x_i - y_j||^2 /eps *log2e ----------------
__global__ void __launch_bounds__(256) compute_C(const float* __restrict__ x,
                                                 const float* __restrict__ y) {
    __shared__ float xt[64 * 68];
    __shared__ float yt[64 * 68];

    const int i0 = blockIdx.y * 64;
    const int j0 = blockIdx.x * 64;
    const int t  = threadIdx.x;

    for (int idx = t; idx < 64 * 64; idx += 256) {
        int r = idx >> 6, c = idx & 63;
        xt[c * 68 + r] = x[(i0 + r) * DIMS + c];
        yt[c * 68 + r] = y[(j0 + r) * DIMS + c];
    }
    __syncthreads();

    const int tx = t & 15;
    const int ty = t >> 4;

    float acc[4][4];
#pragma unroll
    for (int a = 0; a < 4; a++)
#pragma unroll
        for (int b = 0; b < 4; b++) acc[a][b] = 0.f;

#pragma unroll
    for (int d = 0; d < 64; d++) {
        float4 xv = *(const float4*)&xt[d * 68 + ty * 4];
        float4 yv = *(const float4*)&yt[d * 68 + tx * 4];
        float xs_[4] = {xv.x, xv.y, xv.z, xv.w};
        float ys_[4] = {yv.x, yv.y, yv.z, yv.w};
#pragma unroll
        for (int a = 0; a < 4; a++)
#pragma unroll
            for (int b = 0; b < 4; b++) {
                float dd = xs_[a] - ys_[b];
                acc[a][b] = fmaf(dd, dd, acc[a][b]);
            }
    }

    __syncthreads();
    float* cts = xt;

#pragma unroll
    for (int a = 0; a < 4; a++) {
        const int il = ty * 4 + a;
        const int i  = i0 + il;
        float4 ce4;
        ce4.x = -SCALE2 * acc[a][0];
        ce4.y = -SCALE2 * acc[a][1];
        ce4.z = -SCALE2 * acc[a][2];
        ce4.w = -SCALE2 * acc[a][3];
        *(float4*)&g_Ce[(size_t)i * N_PTS + j0 + tx * 4] = ce4;
        cts[il * 65 + tx * 4 + 0] = ce4.x;
        cts[il * 65 + tx * 4 + 1] = ce4.y;
        cts[il * 65 + tx * 4 + 2] = ce4.z;
        cts[il * 65 + tx * 4 + 3] = ce4.w;
    }
    __syncthreads();

    for (int idx = t; idx < 64 * 64; idx += 256) {
        int jl = idx >> 6, il = idx & 63;
        g_Ct[(size_t)(j0 + jl) * N_PTS + i0 + il] = cts[il * 65 + jl];
    }
}

// ---------------- warp-collective online LSE (exp2 domain) ----------------
__device__ __forceinline__ float row_lse2(const float4* __restrict__ C4,
                                          const float4* __restrict__ w4,
                                          int lane) {
    float m = -3.4e38f, s = 0.f;
#pragma unroll
    for (int k = 0; k < 16; k++) {
        float4 c = C4[lane + 32 * k];
        float4 w = w4[lane + 32 * k];
        float t0 = c.x + w.x, t1 = c.y + w.y, t2 = c.z + w.z, t3 = c.w + w.w;
        float mx = fmaxf(fmaxf(t0, t1), fmaxf(t2, t3));
        if (mx > m) { s *= ex2(m - mx); m = mx; }
        s += ex2(t0 - m) + ex2(t1 - m) + ex2(t2 - m) + ex2(t3 - m);
    }
#pragma unroll
    for (int o = 16; o; o >>= 1) {
        float mo = __shfl_xor_sync(0xffffffffu, m, o);
        float so = __shfl_xor_sync(0xffffffffu, s, o);
        float mn = fmaxf(m, mo);
        s = s * ex2(m - mn) + so * ex2(mo - mn);
        m = mn;
    }
    return m + lg2(s);   // log2 LSE
}

// ---------------- persistent Sinkhorn solver ----------------
__global__ void __launch_bounds__(SOLVE_THREADS, 1) solve_kernel(float log_marg) {
    const int tid  = threadIdx.x;
    const int w    = tid >> 5;
    const int lane = tid & 31;
    const int row  = blockIdx.x * 16 + w;

    __shared__ float sdu[16];
    __shared__ float sdv[16];

    // epoch continues across graph replays; all slots ended equal last launch
    unsigned epoch = (unsigned)g_flag[blockIdx.x];

    if (tid < 16) {
        g_usc[blockIdx.x * 16 + tid] = 0.f;
        g_vsc[blockIdx.x * 16 + tid] = 0.f;
    }
    float u_reg = 0.f, v_reg = 0.f;

    bar_sync<false>(++epoch, 0.f);

    const float4* Crow = (const float4*)g_Ce + (size_t)row * (N_PTS / 4);
    const float4* Trow = (const float4*)g_Ct + (size_t)row * (N_PTS / 4);
    const float4* usc4 = (const float4*)g_usc;
    const float4* vsc4 = (const float4*)g_vsc;

    for (int it = 0; it < ITERS; it++) {
        // ---- u update ----
        {
            float lse2 = row_lse2(Crow, vsc4, lane);
            if (lane == 0) {
                float nd = EPSV * log_marg - (EPSV * LN2) * lse2;
                sdu[w] = fabsf(nd - u_reg);
                u_reg = nd;
                g_usc[row] = nd * SCALE2;
            }
        }
        bar_sync<false>(++epoch, 0.f);

        // ---- v update ----
        {
            float lse2 = row_lse2(Trow, usc4, lane);
            if (lane == 0) {
                float nd = EPSV * log_marg - (EPSV * LN2) * lse2;
                sdv[w] = fabsf(nd - v_reg);
                v_reg = nd;
                g_vsc[row] = nd * SCALE2;
            }
        }
        __syncthreads();
        float part = 0.f;
        if (tid == 0) {
#pragma unroll
            for (int k = 0; k < 16; k++) part += sdu[k] + sdv[k];
        }
        // barrier + fused global sum of |du|+|dv|
        float tot = bar_sync<true>(++epoch, part);
        if (tot < THRESH) break;    // identical decision in every block
    }
}

// ---------------- final transport plan + cost ----------------
__global__ void __launch_bounds__(256) pi_cost_kernel(float* __restrict__ pi_out) {
    const int i = blockIdx.x;
    const int t = threadIdx.x;
    const float ui = g_usc[i];
    const float* crow = g_Ce + (size_t)i * N_PTS;
    float* prow = pi_out + (size_t)i * N_PTS;

    float s = 0.f;
#pragma unroll
    for (int k = 0; k < N_PTS / 256; k++) {
        int j = t + k * 256;
        float c = crow[j];
        float p = ex2(c + ui + g_vsc[j]);
        prow[j] = p;
        s = fmaf(p, c, s);          // sum pi * Ce2
    }
    const int lane = t & 31, w = t >> 5;
#pragma unroll
    for (int o = 16; o; o >>= 1) s += __shfl_xor_sync(0xffffffffu, s, o);
    __shared__ float sw[8];
    if (lane == 0) sw[w] = s;
    __syncthreads();
    if (t == 0) {
        float tot = 0.f;
#pragma unroll
        for (int k = 0; k < 8; k++) tot += sw[k];
        g_cost_part[i] = tot * (-EPSV * LN2);   // C = -eps*ln2 * Ce2
    }
}

__global__ void cost_reduce(float* __restrict__ cost_out) {
    __shared__ float sm[1024];
    const int t = threadIdx.x;
    sm[t] = g_cost_part[t] + g_cost_part[t + 1024];
    __syncthreads();
    for (int o = 512; o; o >>= 1) {
        if (t < o) sm[t] += sm[t + o];
        __syncthreads();
    }
    if (t == 0 && cost_out != nullptr) *cost_out = sm[0];
}

// ---------------- launch ----------------
extern "C" void kernel_launch(void* const* d_in, const int* in_sizes, int n_in,
                              void* d_out, int out_size) {
    const float* x = (const float*)d_in[0];
    const float* y = (const float*)d_in[1];
    float* out = (float*)d_out;

    const long long NM = (long long)N_PTS * N_PTS;
    float* cost_out = nullptr;
    float* pi_out   = out;
    if ((long long)out_size >= NM + 1) {
        cost_out = out;
        pi_out   = out + 1;
    }

    const float log_a = (float)log(1.0 / (double)N_PTS + 1e-8);

    dim3 cgrid(N_PTS / 64, N_PTS / 64);
    compute_C<<<cgrid, 256>>>(x, y);
    solve_kernel<<<SOLVE_BLOCKS, SOLVE_THREADS>>>(log_a);
    pi_cost_kernel<<<N_PTS, 256>>>(pi_out);
    cost_reduce<<<1, 1024>>>(cost_out);
}

// round 12
// speedup vs baseline: 1.0983x; 1.0983x over previous
#include <cuda_runtime.h>
#include <math.h>

#define N_PTS 2048
#define DIMS 64
#define EPSV 0.1f
#define INV_EPS 10.0f
#define LOG2E 1.4426950408889634f
#define LN2 0.6931471805599453f
#define SCALE2 (INV_EPS * LOG2E)        /* nat -> exp2 domain incl. 1/eps */
#define ITERS 100
#define THRESH 0.1f

#define SOLVE_BLOCKS 128          // 128 blocks x 16 warps = 2048 warps = one per row
#define SOLVE_THREADS 512

// ---------------- device scratch (static, allocation-free) ----------------
__device__ __align__(16) float g_Ce[N_PTS * N_PTS];   // -C/eps*log2e, row-major [i][j]
__device__ __align__(16) float g_Ct[N_PTS * N_PTS];   // transpose [j][i]
__device__ __align__(16) float g_usc[N_PTS];          // u/eps*log2e
__device__ __align__(16) float g_vsc[N_PTS];          // v/eps*log2e
__device__ float g_cost_part[N_PTS];
__device__ unsigned long long g_flag[SOLVE_BLOCKS];   // packed (float partial << 32 | epoch)

// ---------------- fast exp2/log2 ----------------
__device__ __forceinline__ float ex2(float x) {
    float r; asm("ex2.approx.ftz.f32 %0, %1;" : "=f"(r) : "f"(x)); return r;
}
__device__ __forceinline__ float lg2(float x) {
    float r; asm("lg2.approx.f32 %0, %1;" : "=f"(r) : "f"(x)); return r;
}

// ---------------- flag-array grid barrier, optional fused sum-reduce ----------------
// Every block stores its epoch(+payload) to its own slot; every block's first
// 128 threads each poll one slot. No atomic serialization, no release hop.
template <bool PAYLOAD>
__device__ __forceinline__ float bar_sync(unsigned epoch, float payload) {
    __shared__ float red[4];
    __syncthreads();
    __threadfence();
    if (threadIdx.x == 0) {
        unsigned long long v =
            ((unsigned long long)__float_as_uint(payload) << 32) | (unsigned long long)epoch;
        asm volatile("st.release.gpu.global.u64 [%0], %1;"
                     :: "l"(g_flag + blockIdx.x), "l"(v) : "memory");
    }
    if (threadIdx.x < SOLVE_BLOCKS) {
        unsigned long long v;
        do {
            asm volatile("ld.acquire.gpu.global.u64 %0, [%1];"
                         : "=l"(v) : "l"(g_flag + threadIdx.x) : "memory");
        } while ((unsigned)v != epoch);
        if (PAYLOAD) {
            float ps = __uint_as_float((unsigned)(v >> 32));
#pragma unroll
            for (int o = 16; o; o >>= 1) ps += __shfl_xor_sync(0xffffffffu, ps, o);
            if ((threadIdx.x & 31) == 0) red[threadIdx.x >> 5] = ps;
        }
    }
    __syncthreads();
    if (PAYLOAD) return red[0] + red[1] + red[2] + red[3];
    return 0.f;
}

// ---------------- cost matrix: Ce2[i][j] = -||x_i - y_j||^2 /eps *log2e ----------------
__global__ void __launch_bounds__(256) compute_C(const float* __restrict__ x,
                                                 const float* __restrict__ y) {
    __shared__ float xt[64 * 68];
    __shared__ float yt[64 * 68];

    const int i0 = blockIdx.y * 64;
    const int j0 = blockIdx.x * 64;
    const int t  = threadIdx.x;

    for (int idx = t; idx < 64 * 64; idx += 256) {
        int r = idx >> 6, c = idx & 63;
        xt[c * 68 + r] = x[(i0 + r) * DIMS + c];
        yt[c * 68 + r] = y[(j0 + r) * DIMS + c];
    }
    __syncthreads();

    const int tx = t & 15;
    const int ty = t >> 4;

    float acc[4][4];
#pragma unroll
    for (int a = 0; a < 4; a++)
#pragma unroll
        for (int b = 0; b < 4; b++) acc[a][b] = 0.f;

#pragma unroll
    for (int d = 0; d < 64; d++) {
        float4 xv = *(const float4*)&xt[d * 68 + ty * 4];
        float4 yv = *(const float4*)&yt[d * 68 + tx * 4];
        float xs_[4] = {xv.x, xv.y, xv.z, xv.w};
        float ys_[4] = {yv.x, yv.y, yv.z, yv.w};
#pragma unroll
        for (int a = 0; a < 4; a++)
#pragma unroll
            for (int b = 0; b < 4; b++) {
                float dd = xs_[a] - ys_[b];
                acc[a][b] = fmaf(dd, dd, acc[a][b]);
            }
    }

    __syncthreads();
    float* cts = xt;

#pragma unroll
    for (int a = 0; a < 4; a++) {
        const int il = ty * 4 + a;
        const int i  = i0 + il;
        float4 ce4;
        ce4.x = -SCALE2 * acc[a][0];
        ce4.y = -SCALE2 * acc[a][1];
        ce4.z = -SCALE2 * acc[a][2];
        ce4.w = -SCALE2 * acc[a][3];
        *(float4*)&g_Ce[(size_t)i * N_PTS + j0 + tx * 4] = ce4;
        cts[il * 65 + tx * 4 + 0] = ce4.x;
        cts[il * 65 + tx * 4 + 1] = ce4.y;
        cts[il * 65 + tx * 4 + 2] = ce4.z;
        cts[il * 65 + tx * 4 + 3] = ce4.w;
    }
    __syncthreads();

    for (int idx = t; idx < 64 * 64; idx += 256) {
        int jl = idx >> 6, il = idx & 63;
        g_Ct[(size_t)(j0 + jl) * N_PTS + i0 + il] = cts[il * 65 + jl];
    }
}

// ---------------- warp-collective online LSE (exp2 domain) ----------------
__device__ __forceinline__ float row_lse2(const float4* __restrict__ C4,
                                          const float4* __restrict__ w4,
                                          int lane) {
    float m = -3.4e38f, s = 0.f;
#pragma unroll
    for (int k = 0; k < 16; k++) {
        float4 c = C4[lane + 32 * k];
        float4 w = w4[lane + 32 * k];
        float t0 = c.x + w.x, t1 = c.y + w.y, t2 = c.z + w.z, t3 = c.w + w.w;
        float mx = fmaxf(fmaxf(t0, t1), fmaxf(t2, t3));
        if (mx > m) { s *= ex2(m - mx); m = mx; }
        s += ex2(t0 - m) + ex2(t1 - m) + ex2(t2 - m) + ex2(t3 - m);
    }
#pragma unroll
    for (int o = 16; o; o >>= 1) {
        float mo = __shfl_xor_sync(0xffffffffu, m, o);
        float so = __shfl_xor_sync(0xffffffffu, s, o);
        float mn = fmaxf(m, mo);
        s = s * ex2(m - mn) + so * ex2(mo - mn);
        m = mn;
    }
    return m + lg2(s);   // log2 LSE
}

// ---------------- persistent Sinkhorn solver ----------------
__global__ void __launch_bounds__(SOLVE_THREADS, 1) solve_kernel(float log_marg) {
    const int tid  = threadIdx.x;
    const int w    = tid >> 5;
    const int lane = tid & 31;
    const int row  = blockIdx.x * 16 + w;

    __shared__ float sdu[16];
    __shared__ float sdv[16];

    // epoch continues across graph replays; all slots ended equal last launch
    unsigned epoch = (unsigned)g_flag[blockIdx.x];

    if (tid < 16) {
        g_usc[blockIdx.x * 16 + tid] = 0.f;
        g_vsc[blockIdx.x * 16 + tid] = 0.f;
    }
    float u_reg = 0.f, v_reg = 0.f;

    bar_sync<false>(++epoch, 0.f);

    const float4* Crow = (const float4*)g_Ce + (size_t)row * (N_PTS / 4);
    const float4* Trow = (const float4*)g_Ct + (size_t)row * (N_PTS / 4);
    const float4* usc4 = (const float4*)g_usc;
    const float4* vsc4 = (const float4*)g_vsc;

    for (int it = 0; it < ITERS; it++) {
        // ---- u update ----
        {
            float lse2 = row_lse2(Crow, vsc4, lane);
            if (lane == 0) {
                float nd = EPSV * log_marg - (EPSV * LN2) * lse2;
                sdu[w] = fabsf(nd - u_reg);
                u_reg = nd;
                g_usc[row] = nd * SCALE2;
            }
        }
        bar_sync<false>(++epoch, 0.f);

        // ---- v update ----
        {
            float lse2 = row_lse2(Trow, usc4, lane);
            if (lane == 0) {
                float nd = EPSV * log_marg - (EPSV * LN2) * lse2;
                sdv[w] = fabsf(nd - v_reg);
                v_reg = nd;
                g_vsc[row] = nd * SCALE2;
            }
        }
        __syncthreads();
        float part = 0.f;
        if (tid == 0) {
#pragma unroll
            for (int k = 0; k < 16; k++) part += sdu[k] + sdv[k];
        }
        // barrier + fused global sum of |du|+|dv|
        float tot = bar_sync<true>(++epoch, part);
        if (tot < THRESH) break;    // identical decision in every block
    }
}

// ---------------- final transport plan + cost ----------------
__global__ void __launch_bounds__(256) pi_cost_kernel(float* __restrict__ pi_out) {
    const int i = blockIdx.x;
    const int t = threadIdx.x;
    const float ui = g_usc[i];
    const float* crow = g_Ce + (size_t)i * N_PTS;
    float* prow = pi_out + (size_t)i * N_PTS;

    float s = 0.f;
#pragma unroll
    for (int k = 0; k < N_PTS / 256; k++) {
        int j = t + k * 256;
        float c = crow[j];
        float p = ex2(c + ui + g_vsc[j]);
        prow[j] = p;
        s = fmaf(p, c, s);          // sum pi * Ce2
    }
    const int lane = t & 31, w = t >> 5;
#pragma unroll
    for (int o = 16; o; o >>= 1) s += __shfl_xor_sync(0xffffffffu, s, o);
    __shared__ float sw[8];
    if (lane == 0) sw[w] = s;
    __syncthreads();
    if (t == 0) {
        float tot = 0.f;
#pragma unroll
        for (int k = 0; k < 8; k++) tot += sw[k];
        g_cost_part[i] = tot * (-EPSV * LN2);   // C = -eps*ln2 * Ce2
    }
}

__global__ void cost_reduce(float* __restrict__ cost_out) {
    __shared__ float sm[1024];
    const int t = threadIdx.x;
    sm[t] = g_cost_part[t] + g_cost_part[t + 1024];
    __syncthreads();
    for (int o = 512; o; o >>= 1) {
        if (t < o) sm[t] += sm[t + o];
        __syncthreads();
    }
    if (t == 0 && cost_out != nullptr) *cost_out = sm[0];
}

// ---------------- launch ----------------
extern "C" void kernel_launch(void* const* d_in, const int* in_sizes, int n_in,
                              void* d_out, int out_size) {
    const float* x = (const float*)d_in[0];
    const float* y = (const float*)d_in[1];
    float* out = (float*)d_out;

    const long long NM = (long long)N_PTS * N_PTS;
    float* cost_out = nullptr;
    float* pi_out   = out;
    if ((long long)out_size >= NM + 1) {
        cost_out = out;
        pi_out   = out + 1;
    }

    const float log_a = (float)log(1.0 / (double)N_PTS + 1e-8);

    dim3 cgrid(N_PTS / 64, N_PTS / 64);
    compute_C<<<cgrid, 256>>>(x, y);
    solve_kernel<<<SOLVE_BLOCKS, SOLVE_THREADS>>>(log_a);
    pi_cost_kernel<<<N_PTS, 256>>>(pi_out);
    cost_reduce<<<1, 1024>>>(cost_out);
}

// round 13
// speedup vs baseline: 1.2128x; 1.1042x over previous
#include <cuda_runtime.h>
#include <math.h>

#define N_PTS 2048
#define DIMS 64
#define EPSV 0.1f
#define INV_EPS 10.0f
#define LOG2E 1.4426950408889634f
#define LN2 0.6931471805599453f
#define SCALE2 (INV_EPS * LOG2E)        /* nat -> exp2 domain incl. 1/eps */
#define ITERS 100
#define THRESH 0.1f

#define SOLVE_BLOCKS 128          // 128 blocks x 16 warps = 2048 warps = one per row
#define SOLVE_THREADS 512

// ---------------- device scratch (static, allocation-free) ----------------
__device__ __align__(16) float g_Ce[N_PTS * N_PTS];   // -C/eps*log2e, row-major [i][j]
__device__ __align__(16) float g_Ct[N_PTS * N_PTS];   // transpose [j][i]
__device__ __align__(16) float g_usc[N_PTS];          // u/eps*log2e
__device__ __align__(16) float g_vsc[N_PTS];          // v/eps*log2e
__device__ float g_cost_part[N_PTS];
__device__ unsigned long long g_flag[SOLVE_BLOCKS];   // packed (float partial << 32 | epoch)

// ---------------- fast exp2/log2 ----------------
__device__ __forceinline__ float ex2(float x) {
    float r; asm("ex2.approx.ftz.f32 %0, %1;" : "=f"(r) : "f"(x)); return r;
}
__device__ __forceinline__ float lg2(float x) {
    float r; asm("lg2.approx.f32 %0, %1;" : "=f"(r) : "f"(x)); return r;
}

// ---------------- flag-array grid barrier, optional fused sum-reduce ----------------
// Every block stores its epoch(+payload) to its own slot; every block's first
// 128 threads each poll one slot. No atomic serialization, no release hop.
template <bool PAYLOAD>
__device__ __forceinline__ float bar_sync(unsigned epoch, float payload) {
    __shared__ float red[4];
    __syncthreads();
    __threadfence();
    if (threadIdx.x == 0) {
        unsigned long long v =
            ((unsigned long long)__float_as_uint(payload) << 32) | (unsigned long long)epoch;
        asm volatile("st.release.gpu.global.u64 [%0], %1;"
                     :: "l"(g_flag + blockIdx.x), "l"(v) : "memory");
    }
    if (threadIdx.x < SOLVE_BLOCKS) {
        unsigned long long v;
        do {
            asm volatile("ld.acquire.gpu.global.u64 %0, [%1];"
                         : "=l"(v) : "l"(g_flag + threadIdx.x) : "memory");
        } while ((unsigned)v != epoch);
        if (PAYLOAD) {
            float ps = __uint_as_float((unsigned)(v >> 32));
#pragma unroll
            for (int o = 16; o; o >>= 1) ps += __shfl_xor_sync(0xffffffffu, ps, o);
            if ((threadIdx.x & 31) == 0) red[threadIdx.x >> 5] = ps;
        }
    }
    __syncthreads();
    if (PAYLOAD) return red[0] + red[1] + red[2] + red[3];
    return 0.f;
}

// ---------------- cost matrix: Ce2[i][j] = -||x_i - y_j||^2 /eps *log2e ----------------
__global__ void __launch_bounds__(256) compute_C(const float* __restrict__ x,
                                                 const float* __restrict__ y) {
    __shared__ float xt[64 * 68];
    __shared__ float yt[64 * 68];

    const int i0 = blockIdx.y * 64;
    const int j0 = blockIdx.x * 64;
    const int t  = threadIdx.x;

    for (int idx = t; idx < 64 * 64; idx += 256) {
        int r = idx >> 6, c = idx & 63;
        xt[c * 68 + r] = x[(i0 + r) * DIMS + c];
        yt[c * 68 + r] = y[(j0 + r) * DIMS + c];
    }
    __syncthreads();

    const int tx = t & 15;
    const int ty = t >> 4;

    float acc[4][4];
#pragma unroll
    for (int a = 0; a < 4; a++)
#pragma unroll
        for (int b = 0; b < 4; b++) acc[a][b] = 0.f;

#pragma unroll
    for (int d = 0; d < 64; d++) {
        float4 xv = *(const float4*)&xt[d * 68 + ty * 4];
        float4 yv = *(const float4*)&yt[d * 68 + tx * 4];
        float xs_[4] = {xv.x, xv.y, xv.z, xv.w};
        float ys_[4] = {yv.x, yv.y, yv.z, yv.w};
#pragma unroll
        for (int a = 0; a < 4; a++)
#pragma unroll
            for (int b = 0; b < 4; b++) {
                float dd = xs_[a] - ys_[b];
                acc[a][b] = fmaf(dd, dd, acc[a][b]);
            }
    }

    __syncthreads();
    float* cts = xt;

#pragma unroll
    for (int a = 0; a < 4; a++) {
        const int il = ty * 4 + a;
        const int i  = i0 + il;
        float4 ce4;
        ce4.x = -SCALE2 * acc[a][0];
        ce4.y = -SCALE2 * acc[a][1];
        ce4.z = -SCALE2 * acc[a][2];
        ce4.w = -SCALE2 * acc[a][3];
        *(float4*)&g_Ce[(size_t)i * N_PTS + j0 + tx * 4] = ce4;
        cts[il * 65 + tx * 4 + 0] = ce4.x;
        cts[il * 65 + tx * 4 + 1] = ce4.y;
        cts[il * 65 + tx * 4 + 2] = ce4.z;
        cts[il * 65 + tx * 4 + 3] = ce4.w;
    }
    __syncthreads();

    for (int idx = t; idx < 64 * 64; idx += 256) {
        int jl = idx >> 6, il = idx & 63;
        g_Ct[(size_t)(j0 + jl) * N_PTS + i0 + il] = cts[il * 65 + jl];
    }
}

// ---------------- warp-collective online LSE (exp2 domain) ----------------
__device__ __forceinline__ float row_lse2(const float4* __restrict__ C4,
                                          const float4* __restrict__ w4,
                                          int lane) {
    float m = -3.4e38f, s = 0.f;
#pragma unroll
    for (int k = 0; k < 16; k++) {
        float4 c = C4[lane + 32 * k];
        float4 w = w4[lane + 32 * k];
        float t0 = c.x + w.x, t1 = c.y + w.y, t2 = c.z + w.z, t3 = c.w + w.w;
        float mx = fmaxf(fmaxf(t0, t1), fmaxf(t2, t3));
        if (mx > m) { s *= ex2(m - mx); m = mx; }
        s += ex2(t0 - m) + ex2(t1 - m) + ex2(t2 - m) + ex2(t3 - m);
    }
#pragma unroll
    for (int o = 16; o; o >>= 1) {
        float mo = __shfl_xor_sync(0xffffffffu, m, o);
        float so = __shfl_xor_sync(0xffffffffu, s, o);
        float mn = fmaxf(m, mo);
        s = s * ex2(m - mn) + so * ex2(mo - mn);
        m = mn;
    }
    return m + lg2(s);   // log2 LSE
}

// ---------------- persistent Sinkhorn solver ----------------
__global__ void __launch_bounds__(SOLVE_THREADS, 1) solve_kernel(float log_marg) {
    const int tid  = threadIdx.x;
    const int w    = tid >> 5;
    const int lane = tid & 31;
    const int row  = blockIdx.x * 16 + w;

    __shared__ float sdu[16];
    __shared__ float sdv[16];

    // epoch continues across graph replays; all slots ended equal last launch
    unsigned epoch = (unsigned)g_flag[blockIdx.x];

    if (tid < 16) {
        g_usc[blockIdx.x * 16 + tid] = 0.f;
        g_vsc[blockIdx.x * 16 + tid] = 0.f;
    }
    float u_reg = 0.f, v_reg = 0.f;

    bar_sync<false>(++epoch, 0.f);

    const float4* Crow = (const float4*)g_Ce + (size_t)row * (N_PTS / 4);
    const float4* Trow = (const float4*)g_Ct + (size_t)row * (N_PTS / 4);
    const float4* usc4 = (const float4*)g_usc;
    const float4* vsc4 = (const float4*)g_vsc;

    for (int it = 0; it < ITERS; it++) {
        // ---- u update ----
        {
            float lse2 = row_lse2(Crow, vsc4, lane);
            if (lane == 0) {
                float nd = EPSV * log_marg - (EPSV * LN2) * lse2;
                sdu[w] = fabsf(nd - u_reg);
                u_reg = nd;
                g_usc[row] = nd * SCALE2;
            }
        }
        bar_sync<false>(++epoch, 0.f);

        // ---- v update ----
        {
            float lse2 = row_lse2(Trow, usc4, lane);
            if (lane == 0) {
                float nd = EPSV * log_marg - (EPSV * LN2) * lse2;
                sdv[w] = fabsf(nd - v_reg);
                v_reg = nd;
                g_vsc[row] = nd * SCALE2;
            }
        }
        __syncthreads();
        float part = 0.f;
        if (tid == 0) {
#pragma unroll
            for (int k = 0; k < 16; k++) part += sdu[k] + sdv[k];
        }
        // barrier + fused global sum of |du|+|dv|
        float tot = bar_sync<true>(++epoch, part);
        if (tot < THRESH) break;    // identical decision in every block
    }
}

// ---------------- final transport plan + cost ----------------
__global__ void __launch_bounds__(256) pi_cost_kernel(float* __restrict__ pi_out) {
    const int i = blockIdx.x;
    const int t = threadIdx.x;
    const float ui = g_usc[i];
    const float* crow = g_Ce + (size_t)i * N_PTS;
    float* prow = pi_out + (size_t)i * N_PTS;

    float s = 0.f;
#pragma unroll
    for (int k = 0; k < N_PTS / 256; k++) {
        int j = t + k * 256;
        float c = crow[j];
        float p = ex2(c + ui + g_vsc[j]);
        prow[j] = p;
        s = fmaf(p, c, s);          // sum pi * Ce2
    }
    const int lane = t & 31, w = t >> 5;
#pragma unroll
    for (int o = 16; o; o >>= 1) s += __shfl_xor_sync(0xffffffffu, s, o);
    __shared__ float sw[8];
    if (lane == 0) sw[w] = s;
    __syncthreads();
    if (t == 0) {
        float tot = 0.f;
#pragma unroll
        for (int k = 0; k < 8; k++) tot += sw[k];
        g_cost_part[i] = tot * (-EPSV * LN2);   // C = -eps*ln2 * Ce2
    }
}

__global__ void cost_reduce(float* __restrict__ cost_out) {
    __shared__ float sm[1024];
    const int t = threadIdx.x;
    sm[t] = g_cost_part[t] + g_cost_part[t + 1024];
    __syncthreads();
    for (int o = 512; o; o >>= 1) {
        if (t < o) sm[t] += sm[t + o];
        __syncthreads();
    }
    if (t == 0 && cost_out != nullptr) *cost_out = sm[0];
}

// ---------------- launch ----------------
extern "C" void kernel_launch(void* const* d_in, const int* in_sizes, int n_in,
                              void* d_out, int out_size) {
    const float* x = (const float*)d_in[0];
    const float* y = (const float*)d_in[1];
    float* out = (float*)d_out;

    const long long NM = (long long)N_PTS * N_PTS;
    float* cost_out = nullptr;
    float* pi_out   = out;
    if ((long long)out_size >= NM + 1) {
        cost_out = out;
        pi_out   = out + 1;
    }

    const float log_a = (float)log(1.0 / (double)N_PTS + 1e-8);

    dim3 cgrid(N_PTS / 64, N_PTS / 64);
    compute_C<<<cgrid, 256>>>(x, y);
    solve_kernel<<<SOLVE_BLOCKS, SOLVE_THREADS>>>(log_a);
    pi_cost_kernel<<<N_PTS, 256>>>(pi_out);
    cost_reduce<<<1, 1024>>>(cost_out);
}